// round 1
// baseline (speedup 1.0000x reference)
#include <cuda_runtime.h>
#include <cuda_bf16.h>
#include <cstdint>

// einsum('bis,ie->bse'):
//   inputs    [B=64, I=64, S=4096] f32   (s contiguous)
//   embedding [I=64, E=64]         f32   (e contiguous)
//   out       [B=64, S=4096, E=64] f32   (e contiguous)
//
// Strategy: FFMA GEMM, embedding cached in shared memory (broadcast LDS.128),
// coalesced LDG on inputs across s, 64 fp32 accumulators per thread
// (4 s-values x 16 e-values). FFMA-roofline bound (~31us floor on 148 SMs).

#define BATCH 64
#define ISZ   64
#define SEQ   4096
#define ESZ   64
#define S_TILE 256   // s-values per block
#define THREADS 256

__global__ __launch_bounds__(THREADS, 2)
void embed_gemm_kernel(const float* __restrict__ in,
                       const float* __restrict__ emb,
                       float* __restrict__ out)
{
    __shared__ float emb_sh[ISZ * ESZ];   // 16 KB

    const int tid = threadIdx.x;

    // Stage embedding: 4096 floats = 1024 float4; 256 threads x 4 each.
    {
        const float4* eg = reinterpret_cast<const float4*>(emb);
        float4* es = reinterpret_cast<float4*>(emb_sh);
        #pragma unroll
        for (int j = 0; j < 4; ++j)
            es[tid + THREADS * j] = eg[tid + THREADS * j];
    }
    __syncthreads();

    const int b     = blockIdx.x >> 4;        // 16 s-tiles per batch
    const int stile = blockIdx.x & 15;
    const int s0    = stile * S_TILE;

    const int eg = tid >> 6;    // 0..3  -> e-columns [16*eg, 16*eg+16)
    const int sl = tid & 63;    // 0..63 -> s = s0 + sl + 64*k, k=0..3

    const float* ip = in + (size_t)b * (ISZ * SEQ) + s0 + sl;

    float acc[4][16];
    #pragma unroll
    for (int k = 0; k < 4; ++k)
        #pragma unroll
        for (int e = 0; e < 16; ++e)
            acc[k][e] = 0.0f;

    const float* ebase = emb_sh + eg * 16;

    // Main loop over the contraction axis i.
    #pragma unroll 8
    for (int i = 0; i < ISZ; ++i) {
        const float x0 = ip[0];
        const float x1 = ip[64];
        const float x2 = ip[128];
        const float x3 = ip[192];
        ip += SEQ;

        const float4* e4 = reinterpret_cast<const float4*>(ebase + i * ESZ);
        #pragma unroll
        for (int j = 0; j < 4; ++j) {
            const float4 ev = e4[j];
            acc[0][4*j+0] += x0 * ev.x;  acc[0][4*j+1] += x0 * ev.y;
            acc[0][4*j+2] += x0 * ev.z;  acc[0][4*j+3] += x0 * ev.w;
            acc[1][4*j+0] += x1 * ev.x;  acc[1][4*j+1] += x1 * ev.y;
            acc[1][4*j+2] += x1 * ev.z;  acc[1][4*j+3] += x1 * ev.w;
            acc[2][4*j+0] += x2 * ev.x;  acc[2][4*j+1] += x2 * ev.y;
            acc[2][4*j+2] += x2 * ev.z;  acc[2][4*j+3] += x2 * ev.w;
            acc[3][4*j+0] += x3 * ev.x;  acc[3][4*j+1] += x3 * ev.y;
            acc[3][4*j+2] += x3 * ev.z;  acc[3][4*j+3] += x3 * ev.w;
        }
    }

    // Store: out[b][s0+sl+64k][16*eg .. 16*eg+15], 4 x float4 per s.
    float* op = out + ((size_t)b * SEQ + s0 + sl) * ESZ + eg * 16;
    #pragma unroll
    for (int k = 0; k < 4; ++k) {
        float4* o4 = reinterpret_cast<float4*>(op + (size_t)k * 64 * ESZ);
        #pragma unroll
        for (int j = 0; j < 4; ++j) {
            float4 v;
            v.x = acc[k][4*j+0]; v.y = acc[k][4*j+1];
            v.z = acc[k][4*j+2]; v.w = acc[k][4*j+3];
            o4[j] = v;
        }
    }
}

extern "C" void kernel_launch(void* const* d_in, const int* in_sizes, int n_in,
                              void* d_out, int out_size)
{
    const float* in  = (const float*)d_in[0];   // [64, 64, 4096]
    const float* emb = (const float*)d_in[1];   // [64, 64]
    float* out = (float*)d_out;                 // [64, 4096, 64]

    const int blocks = BATCH * (SEQ / S_TILE);  // 64 * 16 = 1024
    embed_gemm_kernel<<<blocks, THREADS>>>(in, emb, out);
}

// round 2
// speedup vs baseline: 1.0857x; 1.0857x over previous
#include <cuda_runtime.h>
#include <cuda_bf16.h>
#include <cstdint>

// einsum('bis,ie->bse'):
//   inputs    [B=64, I=64, S=4096] f32   (s contiguous)
//   embedding [I=64, E=64]         f32   (e contiguous)
//   out       [B=64, S=4096, E=64] f32   (e contiguous)
//
// FFMA2 (fma.rn.f32x2) GEMM: packed fp32 pairs over the e axis.
// 3-reg FFMA is half-rate on Blackwell (rt_SMSP=2); f32x2 restores the full
// 128 FMA/cyc/SM rate and nearly halves issue count per FMA.

#define BATCH 64
#define ISZ   64
#define SEQ   4096
#define ESZ   64
#define S_TILE 256
#define THREADS 256

typedef unsigned long long u64;

__device__ __forceinline__ u64 pack2(float lo, float hi) {
    u64 r;
    asm("mov.b64 %0, {%1, %2};" : "=l"(r) : "f"(lo), "f"(hi));
    return r;
}

#define FMA2(d, a, b) \
    asm("fma.rn.f32x2 %0, %1, %2, %3;" : "=l"(d) : "l"(a), "l"(b), "l"(d))

__global__ __launch_bounds__(THREADS, 2)
void embed_gemm_f32x2_kernel(const float* __restrict__ in,
                             const float* __restrict__ emb,
                             float* __restrict__ out)
{
    __shared__ float emb_sh[ISZ * ESZ];   // 16 KB

    const int tid = threadIdx.x;

    // Stage embedding: 4096 floats = 1024 float4.
    {
        const float4* eg4 = reinterpret_cast<const float4*>(emb);
        float4* es = reinterpret_cast<float4*>(emb_sh);
        #pragma unroll
        for (int j = 0; j < 4; ++j)
            es[tid + THREADS * j] = eg4[tid + THREADS * j];
    }
    __syncthreads();

    const int b     = blockIdx.x >> 4;
    const int stile = blockIdx.x & 15;
    const int s0    = stile * S_TILE;

    const int eg = tid >> 6;    // e-columns [16*eg, 16*eg+16)
    const int sl = tid & 63;    // s = s0 + sl + 64*k

    const float* ip = in + (size_t)b * (ISZ * SEQ) + s0 + sl;

    // acc[k][j] = packed fp32 pair (e = 16*eg + 2j, 2j+1) for s = s0+sl+64k
    u64 acc[4][8];
    #pragma unroll
    for (int k = 0; k < 4; ++k)
        #pragma unroll
        for (int j = 0; j < 8; ++j)
            acc[k][j] = 0ull;

    const float* ebase = emb_sh + eg * 16;

    #pragma unroll 8
    for (int i = 0; i < ISZ; ++i) {
        const float x0 = ip[0];
        const float x1 = ip[64];
        const float x2 = ip[128];
        const float x3 = ip[192];
        ip += SEQ;

        const u64 xd0 = pack2(x0, x0);
        const u64 xd1 = pack2(x1, x1);
        const u64 xd2 = pack2(x2, x2);
        const u64 xd3 = pack2(x3, x3);

        // 16 embedding floats = 8 packed pairs, via 4x LDS.128 (uniform addr
        // across the warp -> broadcast, conflict-free).
        const ulonglong2* ep =
            reinterpret_cast<const ulonglong2*>(ebase + i * ESZ);
        const ulonglong2 p0 = ep[0];
        const ulonglong2 p1 = ep[1];
        const ulonglong2 p2 = ep[2];
        const ulonglong2 p3 = ep[3];
        const u64 eb0 = p0.x, eb1 = p0.y, eb2 = p1.x, eb3 = p1.y;
        const u64 eb4 = p2.x, eb5 = p2.y, eb6 = p3.x, eb7 = p3.y;

        FMA2(acc[0][0], xd0, eb0); FMA2(acc[0][1], xd0, eb1);
        FMA2(acc[0][2], xd0, eb2); FMA2(acc[0][3], xd0, eb3);
        FMA2(acc[0][4], xd0, eb4); FMA2(acc[0][5], xd0, eb5);
        FMA2(acc[0][6], xd0, eb6); FMA2(acc[0][7], xd0, eb7);

        FMA2(acc[1][0], xd1, eb0); FMA2(acc[1][1], xd1, eb1);
        FMA2(acc[1][2], xd1, eb2); FMA2(acc[1][3], xd1, eb3);
        FMA2(acc[1][4], xd1, eb4); FMA2(acc[1][5], xd1, eb5);
        FMA2(acc[1][6], xd1, eb6); FMA2(acc[1][7], xd1, eb7);

        FMA2(acc[2][0], xd2, eb0); FMA2(acc[2][1], xd2, eb1);
        FMA2(acc[2][2], xd2, eb2); FMA2(acc[2][3], xd2, eb3);
        FMA2(acc[2][4], xd2, eb4); FMA2(acc[2][5], xd2, eb5);
        FMA2(acc[2][6], xd2, eb6); FMA2(acc[2][7], xd2, eb7);

        FMA2(acc[3][0], xd3, eb0); FMA2(acc[3][1], xd3, eb1);
        FMA2(acc[3][2], xd3, eb2); FMA2(acc[3][3], xd3, eb3);
        FMA2(acc[3][4], xd3, eb4); FMA2(acc[3][5], xd3, eb5);
        FMA2(acc[3][6], xd3, eb6); FMA2(acc[3][7], xd3, eb7);
    }

    // Store: pair (2j,2j+1) are consecutive e values -> two pairs = float4.
    float* op = out + ((size_t)b * SEQ + s0 + sl) * ESZ + eg * 16;
    #pragma unroll
    for (int k = 0; k < 4; ++k) {
        ulonglong2* o2 = reinterpret_cast<ulonglong2*>(op + (size_t)k * 64 * ESZ);
        ulonglong2 v0, v1;
        v0.x = acc[k][0]; v0.y = acc[k][1];
        v1.x = acc[k][2]; v1.y = acc[k][3];
        o2[0] = v0; o2[1] = v1;
        ulonglong2 v2, v3;
        v2.x = acc[k][4]; v2.y = acc[k][5];
        v3.x = acc[k][6]; v3.y = acc[k][7];
        o2[2] = v2; o2[3] = v3;
    }
}

extern "C" void kernel_launch(void* const* d_in, const int* in_sizes, int n_in,
                              void* d_out, int out_size)
{
    const float* in  = (const float*)d_in[0];   // [64, 64, 4096]
    const float* emb = (const float*)d_in[1];   // [64, 64]
    float* out = (float*)d_out;                 // [64, 4096, 64]

    const int blocks = BATCH * (SEQ / S_TILE);  // 1024
    embed_gemm_f32x2_kernel<<<blocks, THREADS>>>(in, emb, out);
}

// round 4
// speedup vs baseline: 1.7285x; 1.5920x over previous
#include <cuda_runtime.h>
#include <cuda_bf16.h>
#include <cstdint>

// einsum('bis,ie->bse') via legacy mma.sync bf16 3-term split (sm_80-era HMMA,
// works at compute_100 virtual arch -- tcgen05 is unavailable in this toolchain).
//   inputs    [B=64, I=64, S=4096] f32
//   embedding [I=64, E=64]         f32
//   out       [B=64, S=4096, E=64] f32
//
// D = Ahi*Bhi + Ahi*Blo + Alo*Bhi  (bf16 operands, fp32 accumulate)
// dropped Alo*Blo ~ 2^-18 relative => rel_err ~1e-5.

#define BATCH 64
#define ISZ   64
#define SEQ   4096
#define ESZ   64
#define MTILE 128
#define THREADS 256

// smem: A f32 [64][132] then Bhi u32 [32][72] then Blo u32 [32][72]
#define AS_STRIDE 132
#define BS_STRIDE 72
#define SMEM_A_BYTES  (64 * AS_STRIDE * 4)          // 33792
#define SMEM_BH_OFF   SMEM_A_BYTES
#define SMEM_BL_OFF   (SMEM_A_BYTES + 32 * BS_STRIDE * 4)
#define SMEM_TOTAL    (SMEM_A_BYTES + 2 * 32 * BS_STRIDE * 4)  // 52224

// B = emb pre-packed as k-pair u32 in b-fragment order: Bp[k2][e] =
// {bf16(emb[2k2][e]) in low half, bf16(emb[2k2+1][e]) in high half}
__device__ uint32_t g_Bhi[32 * 64];
__device__ uint32_t g_Blo[32 * 64];

__device__ __forceinline__ uint32_t pack_bf2(float lo_elt, float hi_elt) {
    __nv_bfloat162 h = __floats2bfloat162_rn(lo_elt, hi_elt); // .x -> low bits
    uint32_t u; memcpy(&u, &h, 4);
    return u;
}

__global__ void prep_b_kernel(const float* __restrict__ emb) {
    int idx = blockIdx.x * 128 + threadIdx.x;    // 0..2047
    int k2 = idx >> 6, e = idx & 63;
    float x0 = emb[(2 * k2) * ESZ + e];
    float x1 = emb[(2 * k2 + 1) * ESZ + e];
    uint32_t hp = pack_bf2(x0, x1);
    __nv_bfloat162 hv; memcpy(&hv, &hp, 4);
    float f0 = __bfloat162float(hv.x);
    float f1 = __bfloat162float(hv.y);
    g_Bhi[idx] = hp;
    g_Blo[idx] = pack_bf2(x0 - f0, x1 - f1);
}

#define MMA_BF16(d, a0, a1, a2, a3, b0, b1) \
    asm volatile("mma.sync.aligned.m16n8k16.row.col.f32.bf16.bf16.f32 " \
        "{%0,%1,%2,%3}, {%4,%5,%6,%7}, {%8,%9}, {%0,%1,%2,%3};" \
        : "+f"((d)[0]), "+f"((d)[1]), "+f"((d)[2]), "+f"((d)[3]) \
        : "r"(a0), "r"(a1), "r"(a2), "r"(a3), "r"(b0), "r"(b1))

// split one f32 pair into (hi packed, lo packed)
__device__ __forceinline__ void split_pair(float xa, float xb,
                                           uint32_t& hi, uint32_t& lo) {
    hi = pack_bf2(xa, xb);
    __nv_bfloat162 hv; memcpy(&hv, &hi, 4);
    lo = pack_bf2(xa - __bfloat162float(hv.x), xb - __bfloat162float(hv.y));
}

__global__ __launch_bounds__(THREADS)
void embed_mma_legacy_kernel(const float* __restrict__ in,
                             float* __restrict__ out)
{
    extern __shared__ char smem[];
    float*    As = reinterpret_cast<float*>(smem);
    uint32_t* Bh = reinterpret_cast<uint32_t*>(smem + SMEM_BH_OFF);
    uint32_t* Bl = reinterpret_cast<uint32_t*>(smem + SMEM_BL_OFF);

    const int t = threadIdx.x;
    const int b     = blockIdx.x >> 5;      // 32 s-tiles per batch
    const int stile = blockIdx.x & 31;
    const int s0    = stile * MTILE;

    // ---- stage A tile [64k][128s] f32, coalesced LDG.128 + STS.128 ----
    {
        const float4* gin = reinterpret_cast<const float4*>(
            in + (size_t)b * (ISZ * SEQ) + s0);
        #pragma unroll
        for (int j = 0; j < 8; ++j) {
            int u = j * THREADS + t;            // 0..2047
            int k  = u >> 5;                    // 0..63
            int s4 = u & 31;                    // float4 index within row
            float4 v = gin[(size_t)k * (SEQ / 4) + s4];
            *reinterpret_cast<float4*>(As + k * AS_STRIDE + 4 * s4) = v;
        }
    }
    // ---- stage B pair-packed hi/lo ----
    {
        const uint2* gh = reinterpret_cast<const uint2*>(g_Bhi);
        const uint2* gl = reinterpret_cast<const uint2*>(g_Blo);
        #pragma unroll
        for (int j = 0; j < 4; ++j) {
            int u = j * THREADS + t;            // 0..1023 (uint2 units)
            int rr = u >> 5;                    // 0..31
            int c2 = u & 31;
            uint2 vh = gh[u], vl = gl[u];
            *reinterpret_cast<uint2*>(Bh + rr * BS_STRIDE + 2 * c2) = vh;
            *reinterpret_cast<uint2*>(Bl + rr * BS_STRIDE + 2 * c2) = vl;
        }
    }
    __syncthreads();

    const int w    = t >> 5;
    const int lane = t & 31;
    const int r  = lane >> 2;     // 0..7 : fragment row / b-frag n offset
    const int cq = lane & 3;      // 0..3 : fragment col group
    const int sl = 16 * w + r;
    const int sh = sl + 8;

    float acc[8][4];
    #pragma unroll
    for (int nt = 0; nt < 8; ++nt)
        #pragma unroll
        for (int q = 0; q < 4; ++q) acc[nt][q] = 0.0f;

    #pragma unroll
    for (int ks = 0; ks < 4; ++ks) {
        const int ka = ks * 16 + 2 * cq;
        const float* A0 = As + (ka    ) * AS_STRIDE;
        const float* A1 = As + (ka + 1) * AS_STRIDE;
        const float* A8 = As + (ka + 8) * AS_STRIDE;
        const float* A9 = As + (ka + 9) * AS_STRIDE;

        uint32_t a0h, a1h, a2h, a3h, a0l, a1l, a2l, a3l;
        split_pair(A0[sl], A1[sl], a0h, a0l);
        split_pair(A0[sh], A1[sh], a1h, a1l);
        split_pair(A8[sl], A9[sl], a2h, a2l);
        split_pair(A8[sh], A9[sh], a3h, a3l);

        const uint32_t* bh0 = Bh + (ks * 8 + cq) * BS_STRIDE + r;
        const uint32_t* bh1 = Bh + (ks * 8 + cq + 4) * BS_STRIDE + r;
        const uint32_t* bl0 = Bl + (ks * 8 + cq) * BS_STRIDE + r;
        const uint32_t* bl1 = Bl + (ks * 8 + cq + 4) * BS_STRIDE + r;

        #pragma unroll
        for (int nt = 0; nt < 8; ++nt) {
            const uint32_t b0h = bh0[nt * 8];
            const uint32_t b1h = bh1[nt * 8];
            const uint32_t b0l = bl0[nt * 8];
            const uint32_t b1l = bl1[nt * 8];
            MMA_BF16(acc[nt], a0h, a1h, a2h, a3h, b0h, b1h);
            MMA_BF16(acc[nt], a0h, a1h, a2h, a3h, b0l, b1l);
            MMA_BF16(acc[nt], a0l, a1l, a2l, a3l, b0h, b1h);
        }
    }

    // ---- epilogue: c0,c1 -> row sl ; c2,c3 -> row sh ----
    float* orow  = out + ((size_t)b * SEQ + s0 + sl) * ESZ;
    float* orow8 = out + ((size_t)b * SEQ + s0 + sh) * ESZ;
    #pragma unroll
    for (int nt = 0; nt < 8; ++nt) {
        *reinterpret_cast<float2*>(orow  + nt * 8 + 2 * cq) =
            make_float2(acc[nt][0], acc[nt][1]);
        *reinterpret_cast<float2*>(orow8 + nt * 8 + 2 * cq) =
            make_float2(acc[nt][2], acc[nt][3]);
    }
}

extern "C" void kernel_launch(void* const* d_in, const int* in_sizes, int n_in,
                              void* d_out, int out_size)
{
    const float* in  = (const float*)d_in[0];   // [64, 64, 4096]
    const float* emb = (const float*)d_in[1];   // [64, 64]
    float* out = (float*)d_out;                 // [64, 4096, 64]

    cudaFuncSetAttribute(embed_mma_legacy_kernel,
                         cudaFuncAttributeMaxDynamicSharedMemorySize, SMEM_TOTAL);

    prep_b_kernel<<<16, 128>>>(emb);
    const int blocks = BATCH * (SEQ / MTILE);   // 2048
    embed_mma_legacy_kernel<<<blocks, THREADS, SMEM_TOTAL>>>(in, out);
}

// round 5
// speedup vs baseline: 2.1111x; 1.2214x over previous
#include <cuda_runtime.h>
#include <cuda_bf16.h>
#include <cstdint>
#include <cstring>

// einsum('bis,ie->bse') via mma.sync bf16 3-term split, single kernel.
//   inputs    [B=64, I=64, S=4096] f32
//   embedding [I=64, E=64]         f32
//   out       [B=64, S=4096, E=64] f32
//
// D = Ahi*Bhi + Ahi*Blo + Alo*Bhi  (bf16 operands, fp32 accumulate)
// rel err ~3e-6 (validated round 4).
//
// vs round 4: (1) 2 m-tiles per warp -> B-fragment LDS bytes per output
// halved; (2) A fragments loaded directly from global (4 full 32B sectors
// per LDG.32) -> A staging pipeline deleted; (3) B hi/lo split done in-CTA
// during smem staging -> no prep kernel launch.

#define BATCH 64
#define ISZ   64
#define SEQ   4096
#define ESZ   64
#define MTILE 256        // s per CTA
#define THREADS 256

#define BS_STRIDE 72     // u32 words per k2-row; bank = (8*k2 + e) % 32
#define SMEM_BH_OFF 0
#define SMEM_BL_OFF (32 * BS_STRIDE * 4)
#define SMEM_TOTAL  (2 * 32 * BS_STRIDE * 4)   // 18432 B

__device__ __forceinline__ uint32_t pack_bf2(float a, float b) {
    __nv_bfloat162 h = __floats2bfloat162_rn(a, b);  // .x -> low 16 bits
    uint32_t u; memcpy(&u, &h, 4);
    return u;
}

// split one f32 pair into (hi packed bf16x2, lo packed bf16x2)
__device__ __forceinline__ void split_pair(float xa, float xb,
                                           uint32_t& hi, uint32_t& lo) {
    hi = pack_bf2(xa, xb);
    __nv_bfloat162 hv; memcpy(&hv, &hi, 4);
    lo = pack_bf2(xa - __bfloat162float(hv.x), xb - __bfloat162float(hv.y));
}

#define MMA_BF16(d, a0, a1, a2, a3, b0, b1) \
    asm volatile("mma.sync.aligned.m16n8k16.row.col.f32.bf16.bf16.f32 " \
        "{%0,%1,%2,%3}, {%4,%5,%6,%7}, {%8,%9}, {%0,%1,%2,%3};" \
        : "+f"((d)[0]), "+f"((d)[1]), "+f"((d)[2]), "+f"((d)[3]) \
        : "r"(a0), "r"(a1), "r"(a2), "r"(a3), "r"(b0), "r"(b1))

__global__ __launch_bounds__(THREADS, 2)
void embed_mma_kernel(const float* __restrict__ in,
                      const float* __restrict__ emb,
                      float* __restrict__ out)
{
    extern __shared__ char smem[];
    uint32_t* Bh = reinterpret_cast<uint32_t*>(smem + SMEM_BH_OFF);
    uint32_t* Bl = reinterpret_cast<uint32_t*>(smem + SMEM_BL_OFF);

    const int t = threadIdx.x;
    const int b     = blockIdx.x >> 4;      // 16 s-tiles per batch
    const int stile = blockIdx.x & 15;
    const int s0    = stile * MTILE;

    // ---- stage B: read emb f32, split hi/lo, pack k-pairs ----
    // Bp[k2][e] = pack(emb[2k2][e], emb[2k2+1][e]); 32 x 64 u32 per array.
    {
        #pragma unroll
        for (int j = 0; j < 8; ++j) {
            int idx = j * THREADS + t;      // 0..2047
            int k2 = idx >> 6, e = idx & 63;
            float x0 = emb[(2 * k2) * ESZ + e];
            float x1 = emb[(2 * k2 + 1) * ESZ + e];
            uint32_t hp, lp;
            split_pair(x0, x1, hp, lp);
            Bh[k2 * BS_STRIDE + e] = hp;
            Bl[k2 * BS_STRIDE + e] = lp;
        }
    }
    __syncthreads();

    const int w    = t >> 5;
    const int lane = t & 31;
    const int r  = lane >> 2;     // 0..7
    const int cq = lane & 3;      // 0..3

    // warp covers s rows [s0+32w, s0+32w+32): m-tile 0 at +0, m-tile 1 at +16
    const float* Ab = in + (size_t)b * (ISZ * SEQ) + s0 + 32 * w + r;

    float acc[2][8][4];
    #pragma unroll
    for (int mt = 0; mt < 2; ++mt)
        #pragma unroll
        for (int nt = 0; nt < 8; ++nt)
            #pragma unroll
            for (int q = 0; q < 4; ++q) acc[mt][nt][q] = 0.0f;

    #pragma unroll
    for (int ks = 0; ks < 4; ++ks) {
        const int ka = ks * 16 + 2 * cq;
        const float* P0 = Ab + (size_t)(ka    ) * SEQ;
        const float* P1 = Ab + (size_t)(ka + 1) * SEQ;
        const float* P8 = Ab + (size_t)(ka + 8) * SEQ;
        const float* P9 = Ab + (size_t)(ka + 9) * SEQ;

        // ---- A loads (direct from global), both m-tiles, batched for MLP ----
        float v00 = P0[0],  v10 = P1[0],  v08 = P0[8],  v18 = P1[8];
        float v80 = P8[0],  v90 = P9[0],  v88 = P8[8],  v98 = P9[8];
        float u00 = P0[16], u10 = P1[16], u08 = P0[24], u18 = P1[24];
        float u80 = P8[16], u90 = P9[16], u88 = P8[24], u98 = P9[24];

        // ---- B fragment loads (shared by both m-tiles) ----
        const uint32_t* bh0 = Bh + (ks * 8 + cq) * BS_STRIDE + r;
        const uint32_t* bh1 = Bh + (ks * 8 + cq + 4) * BS_STRIDE + r;
        const uint32_t* bl0 = Bl + (ks * 8 + cq) * BS_STRIDE + r;
        const uint32_t* bl1 = Bl + (ks * 8 + cq + 4) * BS_STRIDE + r;
        uint32_t B0h[8], B1h[8], B0l[8], B1l[8];
        #pragma unroll
        for (int nt = 0; nt < 8; ++nt) {
            B0h[nt] = bh0[nt * 8];
            B1h[nt] = bh1[nt * 8];
            B0l[nt] = bl0[nt * 8];
            B1l[nt] = bl1[nt * 8];
        }

        // ---- m-tile 0 ----
        {
            uint32_t a0h, a1h, a2h, a3h, a0l, a1l, a2l, a3l;
            split_pair(v00, v10, a0h, a0l);
            split_pair(v08, v18, a1h, a1l);
            split_pair(v80, v90, a2h, a2l);
            split_pair(v88, v98, a3h, a3l);
            #pragma unroll
            for (int nt = 0; nt < 8; ++nt) {
                MMA_BF16(acc[0][nt], a0h, a1h, a2h, a3h, B0h[nt], B1h[nt]);
                MMA_BF16(acc[0][nt], a0h, a1h, a2h, a3h, B0l[nt], B1l[nt]);
                MMA_BF16(acc[0][nt], a0l, a1l, a2l, a3l, B0h[nt], B1h[nt]);
            }
        }
        // ---- m-tile 1 ----
        {
            uint32_t a0h, a1h, a2h, a3h, a0l, a1l, a2l, a3l;
            split_pair(u00, u10, a0h, a0l);
            split_pair(u08, u18, a1h, a1l);
            split_pair(u80, u90, a2h, a2l);
            split_pair(u88, u98, a3h, a3l);
            #pragma unroll
            for (int nt = 0; nt < 8; ++nt) {
                MMA_BF16(acc[1][nt], a0h, a1h, a2h, a3h, B0h[nt], B1h[nt]);
                MMA_BF16(acc[1][nt], a0h, a1h, a2h, a3h, B0l[nt], B1l[nt]);
                MMA_BF16(acc[1][nt], a0l, a1l, a2l, a3l, B0h[nt], B1h[nt]);
            }
        }
    }

    // ---- epilogue ----
    #pragma unroll
    for (int mt = 0; mt < 2; ++mt) {
        const size_t srow = (size_t)b * SEQ + s0 + 32 * w + 16 * mt + r;
        float* orow  = out + srow * ESZ;
        float* orow8 = out + (srow + 8) * ESZ;
        #pragma unroll
        for (int nt = 0; nt < 8; ++nt) {
            *reinterpret_cast<float2*>(orow  + nt * 8 + 2 * cq) =
                make_float2(acc[mt][nt][0], acc[mt][nt][1]);
            *reinterpret_cast<float2*>(orow8 + nt * 8 + 2 * cq) =
                make_float2(acc[mt][nt][2], acc[mt][nt][3]);
        }
    }
}

extern "C" void kernel_launch(void* const* d_in, const int* in_sizes, int n_in,
                              void* d_out, int out_size)
{
    const float* in  = (const float*)d_in[0];   // [64, 64, 4096]
    const float* emb = (const float*)d_in[1];   // [64, 64]
    float* out = (float*)d_out;                 // [64, 4096, 64]

    const int blocks = BATCH * (SEQ / MTILE);   // 64 * 16 = 1024
    embed_mma_kernel<<<blocks, THREADS, SMEM_TOTAL>>>(in, emb, out);
}